// round 6
// baseline (speedup 1.0000x reference)
#include <cuda_runtime.h>

typedef unsigned long long u64;

#define HW   64
#define F    64
#define D    75
#define KR   5
#define SXW  68          // 64 + 4 halo
#define NROW 15          // 3 channels * 5 kernel rows
#define NTHR 256

// persistent weight transpose + norms (written by prep, read by main)
__device__ __align__(16) float2 g_WT[D * 32];   // [d][fp] = (W[2fp][d], W[2fp+1][d])
__device__ __align__(16) float2 g_w2[32];       // per-pair squared norms

// ---------------- prep: transpose W once, compute w2 ----------------
__global__ __launch_bounds__(NTHR)
void prep_kernel(const float* __restrict__ W) {
    __shared__ float sW[F * D];
    const int tid = threadIdx.x;

    for (int i = tid; i < F * D; i += NTHR) sW[i] = W[i];   // coalesced
    __syncthreads();

    int j = blockIdx.x * NTHR + tid;        // 16*256 = 4096 >= 2400
    if (j < D * 32) {
        int d  = j >> 5;
        int fp = j & 31;
        g_WT[j] = make_float2(sW[(2 * fp) * D + d], sW[(2 * fp + 1) * D + d]);
    }

    if (blockIdx.x == 0 && tid < 32) {
        float a = 0.f, b = 0.f;
        #pragma unroll
        for (int d = 0; d < D; d++) {
            float wa = sW[(2 * tid) * D + d];
            float wb = sW[(2 * tid + 1) * D + d];
            a += wa * wa;
            b += wb * wb;
        }
        g_w2[tid] = make_float2(a, b);
    }
}

// ---------------- main kernel ----------------
// shared layout (u64 units)
#define OFF_WP  0        // weight pairs [75][32] u64 = 2400
#define OFF_XP  2400     // patch dup    [15][68] u64 = 1020
#define OFF_X2  3420     // x2: 64 floats             = 32
#define OFF_W2  3452     // w2 pairs: 32 u64          = 32
#define SMEM_U64 3484    // 27872 B

__global__ __launch_bounds__(NTHR, 4)
void euclid2d_kernel(const float* __restrict__ x,
                     float* __restrict__ out) {
    __shared__ __align__(16) u64 S[SMEM_U64];
    float* Sf = (float*)S;

    const int tid  = threadIdx.x;
    const int lane = tid & 31;
    const int w    = tid >> 5;          // warp 0..7 -> pixels w*8..w*8+7
    const int ho   = blockIdx.x;        // 0..63
    const int n    = blockIdx.y;        // 0..7

    // ---- weight pairs: fully coalesced 16B loads ----
    {
        const ulonglong2* src = (const ulonglong2*)g_WT;
        ulonglong2* dst = (ulonglong2*)&S[OFF_WP];
        #pragma unroll
        for (int k = 0; k < 5; k++) {
            int j = tid + k * NTHR;     // 1200 x 16B
            if (j < 1200) dst[j] = src[j];
        }
    }
    if (tid < 32) S[OFF_W2 + tid] = ((const u64*)g_w2)[tid];

    // ---- patch tile (duplicated pairs), rows = c*5+kh ----
    const int y0 = ho - 2;
    #pragma unroll
    for (int k = 0; k < 4; k++) {
        int i = tid + k * NTHR;          // 0..1019
        if (i < NROW * SXW) {
            int row = i / SXW;
            int col = i % SXW;
            int c  = row / KR;
            int kh = row % KR;
            int gy = y0 + kh;
            int gx = col - 2;
            float v = 0.0f;
            if (gy >= 0 && gy < HW && gx >= 0 && gx < HW)
                v = x[((n * 3 + c) * HW + gy) * HW + gx];
            u64 p;
            asm("mov.b64 %0, {%1, %1};" : "=l"(p) : "f"(v));
            S[OFF_XP + i] = p;
        }
    }
    __syncthreads();

    // ---- x2 per pixel: 4 threads/pixel, butterfly shfl reduce ----
    {
        const int p = tid >> 2;     // pixel 0..63
        const int q = tid & 3;
        float s = 0.0f;
        #pragma unroll
        for (int k = 0; k < 19; k++) {
            int d = q + 4 * k;
            if (d < D) {
                int row = d / KR, kw = d % KR;
                float v = Sf[(OFF_XP + row * SXW + p + kw) * 2];
                s += v * v;
            }
        }
        s += __shfl_xor_sync(0xffffffffu, s, 1);
        s += __shfl_xor_sync(0xffffffffu, s, 2);
        if (q == 0) Sf[OFF_X2 * 2 + p] = s;
    }
    __syncthreads();

    // ---- main loop: lane = filter pair, thread = 8 pixels ----
    u64 acc[8];
    #pragma unroll
    for (int p = 0; p < 8; p++) acc[p] = 0ULL;

    #pragma unroll
    for (int row = 0; row < NROW; row++) {
        const ulonglong2* prow =
            (const ulonglong2*)&S[OFF_XP + row * SXW + w * 8];
        ulonglong2 P2[6];
        #pragma unroll
        for (int t = 0; t < 6; t++) P2[t] = prow[t];       // LDS.128 broadcast
        const u64* Pu = (const u64*)P2;
        #pragma unroll
        for (int kw = 0; kw < KR; kw++) {
            u64 wv = S[OFF_WP + (row * KR + kw) * 32 + lane];   // LDS.64
            #pragma unroll
            for (int p = 0; p < 8; p++)
                asm("fma.rn.f32x2 %0, %1, %2, %0;"
                    : "+l"(acc[p]) : "l"(Pu[kw + p]), "l"(wv));
        }
    }

    // ---- epilogue: res = acc - 0.5*(x2+w2); direct 32B-sector STG ----
    u64 w2l = S[OFF_W2 + lane];
    u64 nh;
    { float mh = -0.5f; asm("mov.b64 %0, {%1, %1};" : "=l"(nh) : "f"(mh)); }

    float lo[8], hi[8];
    #pragma unroll
    for (int p = 0; p < 8; p++) {
        float x2 = Sf[OFF_X2 * 2 + w * 8 + p];
        u64 x2d, s, r = acc[p];
        asm("mov.b64 %0, {%1, %1};" : "=l"(x2d) : "f"(x2));
        asm("add.rn.f32x2 %0, %1, %2;" : "=l"(s) : "l"(x2d), "l"(w2l));
        asm("fma.rn.f32x2 %0, %1, %2, %0;" : "+l"(r) : "l"(s), "l"(nh));
        asm("mov.b64 {%0, %1}, %2;" : "=f"(lo[p]), "=f"(hi[p]) : "l"(r));
    }

    const int f0 = 2 * lane;
    float* op0 = out + (((long)(n * F + f0) * HW + ho) * HW) + w * 8;
    float* op1 = op0 + (long)HW * HW;

    *(float4*)(op0)     = make_float4(lo[0], lo[1], lo[2], lo[3]);
    *(float4*)(op0 + 4) = make_float4(lo[4], lo[5], lo[6], lo[7]);
    *(float4*)(op1)     = make_float4(hi[0], hi[1], hi[2], hi[3]);
    *(float4*)(op1 + 4) = make_float4(hi[4], hi[5], hi[6], hi[7]);
}

extern "C" void kernel_launch(void* const* d_in, const int* in_sizes, int n_in,
                              void* d_out, int out_size) {
    const float* x = (const float*)d_in[0];
    const float* W = (const float*)d_in[1];
    float* out = (float*)d_out;

    prep_kernel<<<16, NTHR>>>(W);
    dim3 grid(HW, 8);    // (ho, n) = 512 CTAs
    euclid2d_kernel<<<grid, NTHR>>>(x, out);
}

// round 7
// speedup vs baseline: 1.2262x; 1.2262x over previous
#include <cuda_runtime.h>

typedef unsigned long long u64;

#define HW   64
#define F    64
#define D    75
#define KR   5
#define SXW  68          // 64 + 4 halo
#define NROW 15
#define NTHR 128

// shared layout (u64 units)
#define OFF_SCR 0        // phase1: W linear (4800 f32 = 2400 u64)
                         // phase2: w2 partials at u64 2200..2328
                         // phase3: Slo[64][33] f32 (=1056 u64) + Shi at f32 2112
#define OFF_WP  2400     // weight pairs [75][32] u64 = 2400
#define OFF_XP  4800     // patch dup    [15][68] u64 = 1020
#define OFF_W2  5820     // w2 pairs: 32 u64
#define OFF_X2  5852     // x2: 64 f32 = 32 u64
#define SMEM_U64 5884    // 47072 B

#define OFF_SW  2200     // (u64) w2 partials [4][32]
#define FLO     0        // (f32) Slo base
#define FHI     2112     // (f32) Shi base

__global__ __launch_bounds__(NTHR, 4)
void euclid2d_kernel(const float* __restrict__ x,
                     const float* __restrict__ W,
                     float* __restrict__ out) {
    __shared__ __align__(16) u64 S[SMEM_U64];
    float* Sf = (float*)S;

    const int tid  = threadIdx.x;
    const int lane = tid & 31;
    const int w    = tid >> 5;          // warp 0..3 -> pixels w*16..w*16+15
    const int ho   = blockIdx.x;
    const int n    = blockIdx.y;

    // ---- phase A: coalesced loads ----
    {   // W linear: 1200 float4
        const float4* src = (const float4*)W;
        float4* dst = (float4*)&Sf[0];
        #pragma unroll
        for (int k = 0; k < 10; k++) {
            int j = tid + k * NTHR;
            if (j < 1200) dst[j] = src[j];
        }
    }
    {   // patch tile (duplicated pairs)
        const int y0 = ho - 2;
        #pragma unroll
        for (int k = 0; k < 8; k++) {
            int i = tid + k * NTHR;      // 0..1019
            if (i < NROW * SXW) {
                int row = i / SXW;
                int col = i % SXW;
                int gy = y0 + (row % KR);
                int gx = col - 2;
                float v = 0.0f;
                if (gy >= 0 && gy < HW && gx >= 0 && gx < HW)
                    v = x[((n * 3 + (row / KR)) * HW + gy) * HW + gx];
                u64 p;
                asm("mov.b64 %0, {%1, %1};" : "=l"(p) : "f"(v));
                S[OFF_XP + i] = p;
            }
        }
    }
    __syncthreads();

    // ---- phase B: transpose W -> pairs; x2 per pixel ----
    #pragma unroll
    for (int k = 0; k < 19; k++) {
        int j = tid + k * NTHR;          // u64 index d*32+fp
        if (j < 2400) {
            int d  = j >> 5;
            int fp = j & 31;
            float lo = Sf[(2 * fp) * D + d];
            float hi = Sf[(2 * fp + 1) * D + d];
            u64 p;
            asm("mov.b64 %0, {%1, %2};" : "=l"(p) : "f"(lo), "f"(hi));
            S[OFF_WP + j] = p;
        }
    }
    {   // x2: 2 threads per pixel
        const int p = tid >> 1;
        const int q = tid & 1;
        float s = 0.0f;
        #pragma unroll
        for (int k = 0; k < 38; k++) {
            int d = q + 2 * k;
            if (d < D) {
                int row = d / KR, kw = d % KR;
                s += Sf[(OFF_XP + row * SXW + p + kw) * 2]
                   * Sf[(OFF_XP + row * SXW + p + kw) * 2];
            }
        }
        s += __shfl_xor_sync(0xffffffffu, s, 1);
        if (q == 0) Sf[OFF_X2 * 2 + p] = s;
    }
    __syncthreads();

    // ---- phase C: w2 pairs (4-way d-split over 128 threads) ----
    {
        int fp = tid & 31, q = tid >> 5;
        u64 a = 0ULL;
        #pragma unroll
        for (int d_ = 0; d_ < 19; d_++) {
            int d = q + 4 * d_;
            if (d < D) {
                u64 wv = S[OFF_WP + d * 32 + fp];
                asm("fma.rn.f32x2 %0, %1, %1, %0;" : "+l"(a) : "l"(wv));
            }
        }
        S[OFF_SW + q * 32 + fp] = a;     // Wlin region is dead now
    }
    __syncthreads();
    if (tid < 32) {
        u64 a = S[OFF_SW + tid], b = S[OFF_SW + 32 + tid];
        u64 c = S[OFF_SW + 64 + tid], d = S[OFF_SW + 96 + tid];
        u64 r;
        asm("add.rn.f32x2 %0, %1, %2;" : "=l"(r) : "l"(a), "l"(b));
        asm("add.rn.f32x2 %0, %0, %1;" : "+l"(r) : "l"(c));
        asm("add.rn.f32x2 %0, %0, %1;" : "+l"(r) : "l"(d));
        S[OFF_W2 + tid] = r;
    }
    __syncthreads();

    // ---- main loop: lane = filter pair, thread = 16 pixels ----
    u64 acc[16];
    #pragma unroll
    for (int p = 0; p < 16; p++) acc[p] = 0ULL;

    #pragma unroll 1
    for (int row = 0; row < NROW; row++) {
        const ulonglong2* prow =
            (const ulonglong2*)&S[OFF_XP + row * SXW + w * 16];
        ulonglong2 P2[10];
        #pragma unroll
        for (int t = 0; t < 10; t++) P2[t] = prow[t];      // LDS.128 broadcast
        const u64* Pu = (const u64*)P2;                     // 20 u64
        #pragma unroll
        for (int kw = 0; kw < KR; kw++) {
            u64 wv = S[OFF_WP + (row * KR + kw) * 32 + lane];   // LDS.64
            #pragma unroll
            for (int p = 0; p < 16; p++)
                asm("fma.rn.f32x2 %0, %1, %2, %0;"
                    : "+l"(acc[p]) : "l"(Pu[kw + p]), "l"(wv));
        }
    }

    // ---- epilogue: res = acc - 0.5*(x2+w2); split lo/hi padded arrays ----
    {
        u64 w2l = S[OFF_W2 + lane];
        u64 nh;
        { float mh = -0.5f; asm("mov.b64 %0, {%1, %1};" : "=l"(nh) : "f"(mh)); }
        __syncthreads();   // Wlin/partials fully read before Slo/Shi writes
        #pragma unroll
        for (int p = 0; p < 16; p++) {
            int pix = w * 16 + p;
            float x2 = Sf[OFF_X2 * 2 + pix];
            u64 x2d, s, r = acc[p];
            asm("mov.b64 %0, {%1, %1};" : "=l"(x2d) : "f"(x2));
            asm("add.rn.f32x2 %0, %1, %2;" : "=l"(s) : "l"(x2d), "l"(w2l));
            asm("fma.rn.f32x2 %0, %1, %2, %0;" : "+l"(r) : "l"(s), "l"(nh));
            float lo, hi;
            asm("mov.b64 {%0, %1}, %2;" : "=f"(lo), "=f"(hi) : "l"(r));
            Sf[FLO + pix * 33 + lane] = lo;   // conflict-free STS.32
            Sf[FHI + pix * 33 + lane] = hi;
        }
    }
    __syncthreads();

    // ---- store: lane = pixel (coalesced 128B STG), fp column LDS (no conflicts) ----
    #pragma unroll
    for (int k = 0; k < 8; k++) {
        int fp = w + 4 * k;               // warp w covers fp = w,w+4,...,w+28
        float* o0 = out + (((long)(n * F + 2 * fp)     * HW + ho) * HW);
        float* o1 = out + (((long)(n * F + 2 * fp + 1) * HW + ho) * HW);
        #pragma unroll
        for (int half = 0; half < 2; half++) {
            int pix = half * 32 + lane;
            o0[pix] = Sf[FLO + pix * 33 + fp];
            o1[pix] = Sf[FHI + pix * 33 + fp];
        }
    }
}

extern "C" void kernel_launch(void* const* d_in, const int* in_sizes, int n_in,
                              void* d_out, int out_size) {
    const float* x = (const float*)d_in[0];
    const float* W = (const float*)d_in[1];
    float* out = (float*)d_out;

    dim3 grid(HW, 8);    // (ho, n) = 512 CTAs
    euclid2d_kernel<<<grid, NTHR>>>(x, W, out);
}